// round 5
// baseline (speedup 1.0000x reference)
#include <cuda_runtime.h>

#define F 128
#define N_NODES_MAX 50048
#define N_EDGES_MAX 800000
#define RRELU_SLOPE 0.2291666666666667f

#define BM 128
#define KC 64
#define ASTR 68   // padded A stride in smem (floats)

typedef unsigned long long u64;

// ---------------- device scratch (no allocation allowed) ----------------
__device__ float g_agg[(size_t)N_NODES_MAX * F];
__device__ float g_h[(size_t)N_NODES_MAX * F];
__device__ float g_wt[4 * F * F];         // transposed weights, k-major
__device__ float g_stats[2 * F];          // per-column sum, sumsq
__device__ int   g_deg[N_NODES_MAX + 1];
__device__ int   g_startv[N_NODES_MAX + 1];
__device__ int   g_cursor[N_NODES_MAX];
__device__ int   g_bsum[256];
__device__ int2  g_edges[N_EDGES_MAX];    // (src, weight-bits), sorted by target

// ---------------- f32x2 helpers (sm_100+) ----------------
__device__ __forceinline__ u64 pack2(float v) {
    u64 r; asm("mov.b64 %0, {%1, %1};" : "=l"(r) : "f"(v)); return r;
}
__device__ __forceinline__ void fma2(u64& acc, u64 a, u64 b) {
    asm("fma.rn.f32x2 %0, %1, %2, %0;" : "+l"(acc) : "l"(a), "l"(b));
}
__device__ __forceinline__ float2 unpack2(u64 v) {
    float2 f; asm("mov.b64 {%0, %1}, %2;" : "=f"(f.x), "=f"(f.y) : "l"(v)); return f;
}

// ---------------- CSR build ----------------
__global__ void hist_kernel(const int* __restrict__ ei, int E, int* __restrict__ deg) {
    int i = blockIdx.x * blockDim.x + threadIdx.x;
    if (i < E) atomicAdd(&deg[__ldg(&ei[E + i])], 1);
}

// per-256-chunk exclusive scan + chunk totals
__global__ void scan1_kernel(const int* __restrict__ deg, int* __restrict__ start,
                             int* __restrict__ bsum, int N) {
    __shared__ int s[256];
    int t = threadIdx.x;
    int i = blockIdx.x * 256 + t;
    int v = (i < N) ? deg[i] : 0;
    s[t] = v;
    __syncthreads();
#pragma unroll
    for (int o = 1; o < 256; o <<= 1) {
        int x = (t >= o) ? s[t - o] : 0;
        __syncthreads();
        s[t] += x;
        __syncthreads();
    }
    if (i < N) start[i] = s[t] - v;      // exclusive within chunk
    if (t == 255) bsum[blockIdx.x] = s[255];
}

// exclusive scan of up to 256 chunk totals (single block)
__global__ void scan2_kernel(int* __restrict__ bsum, int B) {
    __shared__ int s[256];
    int t = threadIdx.x;
    int v = (t < B) ? bsum[t] : 0;
    s[t] = v;
    __syncthreads();
#pragma unroll
    for (int o = 1; o < 256; o <<= 1) {
        int x = (t >= o) ? s[t - o] : 0;
        __syncthreads();
        s[t] += x;
        __syncthreads();
    }
    if (t < B) bsum[t] = s[t] - v;
}

__global__ void scan3_kernel(int* __restrict__ start, int* __restrict__ cursor,
                             const int* __restrict__ bsum, int N, int E) {
    int i = blockIdx.x * blockDim.x + threadIdx.x;
    if (i < N) {
        int v = start[i] + __ldg(&bsum[i >> 8]);
        start[i] = v;
        cursor[i] = v;
    }
    if (i == 0) start[N] = E;
}

__global__ void fill_kernel(const int* __restrict__ ei, const float* __restrict__ ew,
                            int E, int* __restrict__ cursor, int2* __restrict__ edges) {
    int i = blockIdx.x * blockDim.x + threadIdx.x;
    if (i >= E) return;
    int tgt = __ldg(&ei[E + i]);
    int pos = atomicAdd(&cursor[tgt], 1);
    edges[pos] = make_int2(__ldg(&ei[i]), __float_as_int(__ldg(&ew[i])));
}

// ---------------- gather aggregation: one warp per node, no atomics ----------------
__global__ void gather_kernel(const float* __restrict__ feat, const int* __restrict__ start,
                              const int2* __restrict__ edges, float* __restrict__ agg, int N) {
    int warp = (blockIdx.x * blockDim.x + threadIdx.x) >> 5;
    if (warp >= N) return;
    int lane = threadIdx.x & 31;
    int s0 = __ldg(&start[warp]);
    int s1 = __ldg(&start[warp + 1]);
    float4 acc = make_float4(0.f, 0.f, 0.f, 0.f);
    int i = s0;
    for (; i + 2 <= s1; i += 2) {
        int2 e0 = __ldg(&edges[i]);
        int2 e1 = __ldg(&edges[i + 1]);
        float4 v0 = *(const float4*)(feat + (size_t)e0.x * F + lane * 4);
        float4 v1 = *(const float4*)(feat + (size_t)e1.x * F + lane * 4);
        float w0 = __int_as_float(e0.y), w1 = __int_as_float(e1.y);
        acc.x = fmaf(v0.x, w0, acc.x); acc.y = fmaf(v0.y, w0, acc.y);
        acc.z = fmaf(v0.z, w0, acc.z); acc.w = fmaf(v0.w, w0, acc.w);
        acc.x = fmaf(v1.x, w1, acc.x); acc.y = fmaf(v1.y, w1, acc.y);
        acc.z = fmaf(v1.z, w1, acc.z); acc.w = fmaf(v1.w, w1, acc.w);
    }
    if (i < s1) {
        int2 e0 = __ldg(&edges[i]);
        float4 v0 = *(const float4*)(feat + (size_t)e0.x * F + lane * 4);
        float w0 = __int_as_float(e0.y);
        acc.x = fmaf(v0.x, w0, acc.x); acc.y = fmaf(v0.y, w0, acc.y);
        acc.z = fmaf(v0.z, w0, acc.z); acc.w = fmaf(v0.w, w0, acc.w);
    }
    *(float4*)(agg + (size_t)warp * F + lane * 4) = acc;
}

// ---------------- weight transpose (all 4 matrices, one launch) ----------------
__global__ void transpose_all(const float* __restrict__ w0, const float* __restrict__ w1,
                              const float* __restrict__ w2, const float* __restrict__ w3,
                              float* __restrict__ out) {
    __shared__ float t[32][33];
    const float* in = (blockIdx.z == 0) ? w0 : (blockIdx.z == 1) ? w1
                    : (blockIdx.z == 2) ? w2 : w3;
    float* o = out + (size_t)blockIdx.z * F * F;
    int bx = blockIdx.x, by = blockIdx.y;
    int x = bx * 32 + threadIdx.x;
    for (int i = threadIdx.y; i < 32; i += 8)
        t[i][threadIdx.x] = in[(by * 32 + i) * F + x];
    __syncthreads();
    for (int i = threadIdx.y; i < 32; i += 8)
        o[(bx * 32 + i) * F + by * 32 + threadIdx.x] = t[threadIdx.x][i];
}

// ---------------- fused dual GEMM: out = A1@W1^T + A2@W2^T + bias ----------------
template<bool STATS>
__global__ void __launch_bounds__(256, 1) gemm_fused(
    const float* __restrict__ A1, const float* __restrict__ A2,
    const float* __restrict__ Wt1, const float* __restrict__ Wt2,
    const float* __restrict__ bias, float* __restrict__ out,
    int N, float* __restrict__ stats)
{
    extern __shared__ float sm[];
    float* sW1 = sm;
    float* sW2 = sm + F * F;
    float* sA1 = sm + 2 * F * F;
    float* sA2 = sA1 + BM * ASTR;

    int tid = threadIdx.x;
    int tx = tid & 15;
    int ty = tid >> 4;
    int row0 = blockIdx.x * BM;

#pragma unroll
    for (int i = 0; i < 16; i++) {
        int j = tid + i * 256;
        ((float4*)sW1)[j] = ((const float4*)Wt1)[j];
        ((float4*)sW2)[j] = ((const float4*)Wt2)[j];
    }

    u64 acc[8][4];
#pragma unroll
    for (int i = 0; i < 8; i++)
#pragma unroll
        for (int p = 0; p < 4; p++) acc[i][p] = 0ULL;

    for (int c0 = 0; c0 < F; c0 += KC) {
        __syncthreads();
#pragma unroll
        for (int i = 0; i < 8; i++) {
            int j = tid + i * 256;
            int r = j >> 4;
            int k4 = (j & 15) << 2;
            float4 v1 = make_float4(0.f, 0.f, 0.f, 0.f), v2 = v1;
            int grow = row0 + r;
            if (grow < N) {
                v1 = *(const float4*)(A1 + (size_t)grow * F + c0 + k4);
                v2 = *(const float4*)(A2 + (size_t)grow * F + c0 + k4);
            }
            *(float4*)(sA1 + r * ASTR + k4) = v1;
            *(float4*)(sA2 + r * ASTR + k4) = v2;
        }
        __syncthreads();

#pragma unroll 4
        for (int k = 0; k < KC; k++) {
            int kk = c0 + k;
            u64 w1[4], w2[4];
#pragma unroll
            for (int p = 0; p < 4; p++) {
                w1[p] = *(const u64*)(sW1 + kk * F + tx * 2 + p * 32);
                w2[p] = *(const u64*)(sW2 + kk * F + tx * 2 + p * 32);
            }
#pragma unroll
            for (int i = 0; i < 8; i++) {
                u64 a1 = pack2(sA1[(ty * 8 + i) * ASTR + k]);
                u64 a2 = pack2(sA2[(ty * 8 + i) * ASTR + k]);
#pragma unroll
                for (int p = 0; p < 4; p++) {
                    fma2(acc[i][p], a1, w1[p]);
                    fma2(acc[i][p], a2, w2[p]);
                }
            }
        }
    }

    float bcols[4][2];
#pragma unroll
    for (int p = 0; p < 4; p++) {
        int c = tx * 2 + p * 32;
        bcols[p][0] = __ldg(&bias[c]);
        bcols[p][1] = __ldg(&bias[c + 1]);
    }

    float csum[4][2] = {{0.f}}, csq[4][2] = {{0.f}};
#pragma unroll
    for (int i = 0; i < 8; i++) {
        int grow = row0 + ty * 8 + i;
        if (grow < N) {
#pragma unroll
            for (int p = 0; p < 4; p++) {
                float2 v = unpack2(acc[i][p]);
                v.x += bcols[p][0];
                v.y += bcols[p][1];
                int c = tx * 2 + p * 32;
                *(float2*)(out + (size_t)grow * F + c) = v;
                if (STATS) {
                    csum[p][0] += v.x; csum[p][1] += v.y;
                    csq[p][0] += v.x * v.x; csq[p][1] += v.y * v.y;
                }
            }
        }
    }

    if (STATS) {
        __syncthreads();
        float* sSum = sA1;
        float* sSq  = sA1 + F;
        if (tid < F) { sSum[tid] = 0.f; sSq[tid] = 0.f; }
        __syncthreads();
#pragma unroll
        for (int p = 0; p < 4; p++) {
            int c = tx * 2 + p * 32;
            atomicAdd(&sSum[c],     csum[p][0]);
            atomicAdd(&sSum[c + 1], csum[p][1]);
            atomicAdd(&sSq[c],      csq[p][0]);
            atomicAdd(&sSq[c + 1],  csq[p][1]);
        }
        __syncthreads();
        if (tid < F) {
            atomicAdd(&stats[tid],     sSum[tid]);
            atomicAdd(&stats[F + tid], sSq[tid]);
        }
    }
}

// ---------------- BatchNorm (batch stats) + RReLU(eval) in place ----------------
__global__ void bn_rrelu_kernel(float* __restrict__ h, const float* __restrict__ stats,
                                const float* __restrict__ gamma, const float* __restrict__ beta,
                                int N) {
    int i = blockIdx.x * blockDim.x + threadIdx.x;
    int total4 = N * (F / 4);
    if (i >= total4) return;
    int c0 = (i * 4) & (F - 1);
    float inv = 1.0f / (float)N;
    float4 v = ((float4*)h)[i];
    float r[4] = {v.x, v.y, v.z, v.w};
#pragma unroll
    for (int j = 0; j < 4; j++) {
        int c = c0 + j;
        float mean = __ldg(&stats[c]) * inv;
        float var  = __ldg(&stats[F + c]) * inv - mean * mean;
        float rs   = rsqrtf(var + 1e-5f);
        float sc   = rs * __ldg(&gamma[c]);
        float sh   = __ldg(&beta[c]) - mean * sc;
        float t = r[j] * sc + sh;
        r[j] = (t >= 0.f) ? t : t * RRELU_SLOPE;
    }
    ((float4*)h)[i] = make_float4(r[0], r[1], r[2], r[3]);
}

// ---------------- launch ----------------
extern "C" void kernel_launch(void* const* d_in, const int* in_sizes, int n_in,
                              void* d_out, int out_size) {
    const float* x      = (const float*)d_in[0];
    const int*   ei     = (const int*)d_in[1];
    const float* ea     = (const float*)d_in[2];
    const float* W1rel  = (const float*)d_in[3];
    const float* b1     = (const float*)d_in[4];
    const float* W1root = (const float*)d_in[5];
    const float* gamma  = (const float*)d_in[6];
    const float* beta   = (const float*)d_in[7];
    const float* W2rel  = (const float*)d_in[8];
    const float* b2     = (const float*)d_in[9];
    const float* W2root = (const float*)d_in[10];
    float* out = (float*)d_out;

    int N = in_sizes[0] / F;
    int E = in_sizes[2];

    float *agg, *h, *wt, *stats;
    int *deg, *startv, *cursor, *bsum;
    int2 *edges;
    cudaGetSymbolAddress((void**)&agg,    g_agg);
    cudaGetSymbolAddress((void**)&h,      g_h);
    cudaGetSymbolAddress((void**)&wt,     g_wt);
    cudaGetSymbolAddress((void**)&stats,  g_stats);
    cudaGetSymbolAddress((void**)&deg,    g_deg);
    cudaGetSymbolAddress((void**)&startv, g_startv);
    cudaGetSymbolAddress((void**)&cursor, g_cursor);
    cudaGetSymbolAddress((void**)&bsum,   g_bsum);
    cudaGetSymbolAddress((void**)&edges,  g_edges);

    const int SMEM = (2 * F * F + 2 * BM * ASTR) * (int)sizeof(float);
    cudaFuncSetAttribute(gemm_fused<true>,  cudaFuncAttributeMaxDynamicSharedMemorySize, SMEM);
    cudaFuncSetAttribute(gemm_fused<false>, cudaFuncAttributeMaxDynamicSharedMemorySize, SMEM);

    // ---- CSR build (once, reused by both layers) ----
    cudaMemsetAsync(deg, 0, (N + 1) * sizeof(int));
    cudaMemsetAsync(stats, 0, 2 * F * sizeof(float));

    int eb = (E + 255) / 256;
    hist_kernel<<<eb, 256>>>(ei, E, deg);
    int nchunks = (N + 255) / 256;
    scan1_kernel<<<nchunks, 256>>>(deg, startv, bsum, N);
    scan2_kernel<<<1, 256>>>(bsum, nchunks);
    scan3_kernel<<<nchunks, 256>>>(startv, cursor, bsum, N, E);
    fill_kernel<<<eb, 256>>>(ei, ea, E, cursor, edges);

    transpose_all<<<dim3(4, 4, 4), dim3(32, 8)>>>(W1rel, W1root, W2rel, W2root, wt);

    // ---- layer 1 ----
    int gwb = (N * 32 + 255) / 256;
    gather_kernel<<<gwb, 256>>>(x, startv, edges, agg, N);

    int gblocks = (N + BM - 1) / BM;
    gemm_fused<true><<<gblocks, 256, SMEM>>>(agg, x, wt, wt + F * F, b1, h, N, stats);

    int bnblocks = (N * (F / 4) + 255) / 256;
    bn_rrelu_kernel<<<bnblocks, 256>>>(h, stats, gamma, beta, N);

    // ---- layer 2 ----
    gather_kernel<<<gwb, 256>>>(h, startv, edges, agg, N);

    gemm_fused<false><<<gblocks, 256, SMEM>>>(agg, h, wt + 2 * F * F, wt + 3 * F * F, b2, out, N, nullptr);
}

// round 6
// speedup vs baseline: 1.0003x; 1.0003x over previous
#include <cuda_runtime.h>

#define F 128
#define N_NODES_MAX 50048
#define N_EDGES_MAX 800000
#define RRELU_SLOPE 0.2291666666666667f

#define BM 128
#define KC 64
#define ASTR 68   // padded A stride in smem (floats)

typedef unsigned long long u64;

// ---------------- device scratch (no allocation allowed) ----------------
__device__ float g_agg[(size_t)N_NODES_MAX * F];
__device__ float g_h[(size_t)N_NODES_MAX * F];
__device__ float g_wt[4 * F * F];         // transposed weights, k-major
__device__ float g_stats[2 * F];          // per-column sum, sumsq
__device__ int   g_deg[N_NODES_MAX + 1];
__device__ int   g_startv[N_NODES_MAX + 1];
__device__ int   g_cursor[N_NODES_MAX];
__device__ int   g_bsum[256];
__device__ int2  g_edges[N_EDGES_MAX];    // (src, weight-bits), sorted by target

// ---------------- f32x2 helpers (sm_100+) ----------------
__device__ __forceinline__ u64 pack2(float v) {
    u64 r; asm("mov.b64 %0, {%1, %1};" : "=l"(r) : "f"(v)); return r;
}
__device__ __forceinline__ void fma2(u64& acc, u64 a, u64 b) {
    asm("fma.rn.f32x2 %0, %1, %2, %0;" : "+l"(acc) : "l"(a), "l"(b));
}
__device__ __forceinline__ float2 unpack2(u64 v) {
    float2 f; asm("mov.b64 {%0, %1}, %2;" : "=f"(f.x), "=f"(f.y) : "l"(v)); return f;
}

// ---------------- CSR build ----------------
__global__ void hist_kernel(const int* __restrict__ ei, int E, int* __restrict__ deg) {
    int i = blockIdx.x * blockDim.x + threadIdx.x;
    if (i < E) atomicAdd(&deg[__ldg(&ei[E + i])], 1);
}

// per-256-chunk exclusive scan + chunk totals
__global__ void scan1_kernel(const int* __restrict__ deg, int* __restrict__ start,
                             int* __restrict__ bsum, int N) {
    __shared__ int s[256];
    int t = threadIdx.x;
    int i = blockIdx.x * 256 + t;
    int v = (i < N) ? deg[i] : 0;
    s[t] = v;
    __syncthreads();
#pragma unroll
    for (int o = 1; o < 256; o <<= 1) {
        int x = (t >= o) ? s[t - o] : 0;
        __syncthreads();
        s[t] += x;
        __syncthreads();
    }
    if (i < N) start[i] = s[t] - v;      // exclusive within chunk
    if (t == 255) bsum[blockIdx.x] = s[255];
}

// exclusive scan of up to 256 chunk totals (single block)
__global__ void scan2_kernel(int* __restrict__ bsum, int B) {
    __shared__ int s[256];
    int t = threadIdx.x;
    int v = (t < B) ? bsum[t] : 0;
    s[t] = v;
    __syncthreads();
#pragma unroll
    for (int o = 1; o < 256; o <<= 1) {
        int x = (t >= o) ? s[t - o] : 0;
        __syncthreads();
        s[t] += x;
        __syncthreads();
    }
    if (t < B) bsum[t] = s[t] - v;
}

__global__ void scan3_kernel(int* __restrict__ start, int* __restrict__ cursor,
                             const int* __restrict__ bsum, int N, int E) {
    int i = blockIdx.x * blockDim.x + threadIdx.x;
    if (i < N) {
        int v = start[i] + __ldg(&bsum[i >> 8]);
        start[i] = v;
        cursor[i] = v;
    }
    if (i == 0) start[N] = E;
}

__global__ void fill_kernel(const int* __restrict__ ei, const float* __restrict__ ew,
                            int E, int* __restrict__ cursor, int2* __restrict__ edges) {
    int i = blockIdx.x * blockDim.x + threadIdx.x;
    if (i >= E) return;
    int tgt = __ldg(&ei[E + i]);
    int pos = atomicAdd(&cursor[tgt], 1);
    edges[pos] = make_int2(__ldg(&ei[i]), __float_as_int(__ldg(&ew[i])));
}

// ---------------- gather aggregation: one warp per node, no atomics ----------------
__global__ void gather_kernel(const float* __restrict__ feat, const int* __restrict__ start,
                              const int2* __restrict__ edges, float* __restrict__ agg, int N) {
    int warp = (blockIdx.x * blockDim.x + threadIdx.x) >> 5;
    if (warp >= N) return;
    int lane = threadIdx.x & 31;
    int s0 = __ldg(&start[warp]);
    int s1 = __ldg(&start[warp + 1]);
    float4 acc = make_float4(0.f, 0.f, 0.f, 0.f);
    int i = s0;
    for (; i + 2 <= s1; i += 2) {
        int2 e0 = __ldg(&edges[i]);
        int2 e1 = __ldg(&edges[i + 1]);
        float4 v0 = *(const float4*)(feat + (size_t)e0.x * F + lane * 4);
        float4 v1 = *(const float4*)(feat + (size_t)e1.x * F + lane * 4);
        float w0 = __int_as_float(e0.y), w1 = __int_as_float(e1.y);
        acc.x = fmaf(v0.x, w0, acc.x); acc.y = fmaf(v0.y, w0, acc.y);
        acc.z = fmaf(v0.z, w0, acc.z); acc.w = fmaf(v0.w, w0, acc.w);
        acc.x = fmaf(v1.x, w1, acc.x); acc.y = fmaf(v1.y, w1, acc.y);
        acc.z = fmaf(v1.z, w1, acc.z); acc.w = fmaf(v1.w, w1, acc.w);
    }
    if (i < s1) {
        int2 e0 = __ldg(&edges[i]);
        float4 v0 = *(const float4*)(feat + (size_t)e0.x * F + lane * 4);
        float w0 = __int_as_float(e0.y);
        acc.x = fmaf(v0.x, w0, acc.x); acc.y = fmaf(v0.y, w0, acc.y);
        acc.z = fmaf(v0.z, w0, acc.z); acc.w = fmaf(v0.w, w0, acc.w);
    }
    *(float4*)(agg + (size_t)warp * F + lane * 4) = acc;
}

// ---------------- weight transpose (all 4 matrices, one launch) ----------------
__global__ void transpose_all(const float* __restrict__ w0, const float* __restrict__ w1,
                              const float* __restrict__ w2, const float* __restrict__ w3,
                              float* __restrict__ out) {
    __shared__ float t[32][33];
    const float* in = (blockIdx.z == 0) ? w0 : (blockIdx.z == 1) ? w1
                    : (blockIdx.z == 2) ? w2 : w3;
    float* o = out + (size_t)blockIdx.z * F * F;
    int bx = blockIdx.x, by = blockIdx.y;
    int x = bx * 32 + threadIdx.x;
    for (int i = threadIdx.y; i < 32; i += 8)
        t[i][threadIdx.x] = in[(by * 32 + i) * F + x];
    __syncthreads();
    for (int i = threadIdx.y; i < 32; i += 8)
        o[(bx * 32 + i) * F + by * 32 + threadIdx.x] = t[threadIdx.x][i];
}

// ---------------- fused dual GEMM: out = A1@W1^T + A2@W2^T + bias ----------------
template<bool STATS>
__global__ void __launch_bounds__(256, 1) gemm_fused(
    const float* __restrict__ A1, const float* __restrict__ A2,
    const float* __restrict__ Wt1, const float* __restrict__ Wt2,
    const float* __restrict__ bias, float* __restrict__ out,
    int N, float* __restrict__ stats)
{
    extern __shared__ float sm[];
    float* sW1 = sm;
    float* sW2 = sm + F * F;
    float* sA1 = sm + 2 * F * F;
    float* sA2 = sA1 + BM * ASTR;

    int tid = threadIdx.x;
    int tx = tid & 15;
    int ty = tid >> 4;
    int row0 = blockIdx.x * BM;

#pragma unroll
    for (int i = 0; i < 16; i++) {
        int j = tid + i * 256;
        ((float4*)sW1)[j] = ((const float4*)Wt1)[j];
        ((float4*)sW2)[j] = ((const float4*)Wt2)[j];
    }

    u64 acc[8][4];
#pragma unroll
    for (int i = 0; i < 8; i++)
#pragma unroll
        for (int p = 0; p < 4; p++) acc[i][p] = 0ULL;

    for (int c0 = 0; c0 < F; c0 += KC) {
        __syncthreads();
#pragma unroll
        for (int i = 0; i < 8; i++) {
            int j = tid + i * 256;
            int r = j >> 4;
            int k4 = (j & 15) << 2;
            float4 v1 = make_float4(0.f, 0.f, 0.f, 0.f), v2 = v1;
            int grow = row0 + r;
            if (grow < N) {
                v1 = *(const float4*)(A1 + (size_t)grow * F + c0 + k4);
                v2 = *(const float4*)(A2 + (size_t)grow * F + c0 + k4);
            }
            *(float4*)(sA1 + r * ASTR + k4) = v1;
            *(float4*)(sA2 + r * ASTR + k4) = v2;
        }
        __syncthreads();

#pragma unroll 4
        for (int k = 0; k < KC; k++) {
            int kk = c0 + k;
            u64 w1[4], w2[4];
#pragma unroll
            for (int p = 0; p < 4; p++) {
                w1[p] = *(const u64*)(sW1 + kk * F + tx * 2 + p * 32);
                w2[p] = *(const u64*)(sW2 + kk * F + tx * 2 + p * 32);
            }
#pragma unroll
            for (int i = 0; i < 8; i++) {
                u64 a1 = pack2(sA1[(ty * 8 + i) * ASTR + k]);
                u64 a2 = pack2(sA2[(ty * 8 + i) * ASTR + k]);
#pragma unroll
                for (int p = 0; p < 4; p++) {
                    fma2(acc[i][p], a1, w1[p]);
                    fma2(acc[i][p], a2, w2[p]);
                }
            }
        }
    }

    float bcols[4][2];
#pragma unroll
    for (int p = 0; p < 4; p++) {
        int c = tx * 2 + p * 32;
        bcols[p][0] = __ldg(&bias[c]);
        bcols[p][1] = __ldg(&bias[c + 1]);
    }

    float csum[4][2] = {{0.f}}, csq[4][2] = {{0.f}};
#pragma unroll
    for (int i = 0; i < 8; i++) {
        int grow = row0 + ty * 8 + i;
        if (grow < N) {
#pragma unroll
            for (int p = 0; p < 4; p++) {
                float2 v = unpack2(acc[i][p]);
                v.x += bcols[p][0];
                v.y += bcols[p][1];
                int c = tx * 2 + p * 32;
                *(float2*)(out + (size_t)grow * F + c) = v;
                if (STATS) {
                    csum[p][0] += v.x; csum[p][1] += v.y;
                    csq[p][0] += v.x * v.x; csq[p][1] += v.y * v.y;
                }
            }
        }
    }

    if (STATS) {
        __syncthreads();
        float* sSum = sA1;
        float* sSq  = sA1 + F;
        if (tid < F) { sSum[tid] = 0.f; sSq[tid] = 0.f; }
        __syncthreads();
#pragma unroll
        for (int p = 0; p < 4; p++) {
            int c = tx * 2 + p * 32;
            atomicAdd(&sSum[c],     csum[p][0]);
            atomicAdd(&sSum[c + 1], csum[p][1]);
            atomicAdd(&sSq[c],      csq[p][0]);
            atomicAdd(&sSq[c + 1],  csq[p][1]);
        }
        __syncthreads();
        if (tid < F) {
            atomicAdd(&stats[tid],     sSum[tid]);
            atomicAdd(&stats[F + tid], sSq[tid]);
        }
    }
}

// ---------------- BatchNorm (batch stats) + RReLU(eval) in place ----------------
__global__ void bn_rrelu_kernel(float* __restrict__ h, const float* __restrict__ stats,
                                const float* __restrict__ gamma, const float* __restrict__ beta,
                                int N) {
    int i = blockIdx.x * blockDim.x + threadIdx.x;
    int total4 = N * (F / 4);
    if (i >= total4) return;
    int c0 = (i * 4) & (F - 1);
    float inv = 1.0f / (float)N;
    float4 v = ((float4*)h)[i];
    float r[4] = {v.x, v.y, v.z, v.w};
#pragma unroll
    for (int j = 0; j < 4; j++) {
        int c = c0 + j;
        float mean = __ldg(&stats[c]) * inv;
        float var  = __ldg(&stats[F + c]) * inv - mean * mean;
        float rs   = rsqrtf(var + 1e-5f);
        float sc   = rs * __ldg(&gamma[c]);
        float sh   = __ldg(&beta[c]) - mean * sc;
        float t = r[j] * sc + sh;
        r[j] = (t >= 0.f) ? t : t * RRELU_SLOPE;
    }
    ((float4*)h)[i] = make_float4(r[0], r[1], r[2], r[3]);
}

// ---------------- launch ----------------
extern "C" void kernel_launch(void* const* d_in, const int* in_sizes, int n_in,
                              void* d_out, int out_size) {
    const float* x      = (const float*)d_in[0];
    const int*   ei     = (const int*)d_in[1];
    const float* ea     = (const float*)d_in[2];
    const float* W1rel  = (const float*)d_in[3];
    const float* b1     = (const float*)d_in[4];
    const float* W1root = (const float*)d_in[5];
    const float* gamma  = (const float*)d_in[6];
    const float* beta   = (const float*)d_in[7];
    const float* W2rel  = (const float*)d_in[8];
    const float* b2     = (const float*)d_in[9];
    const float* W2root = (const float*)d_in[10];
    float* out = (float*)d_out;

    int N = in_sizes[0] / F;
    int E = in_sizes[2];

    float *agg, *h, *wt, *stats;
    int *deg, *startv, *cursor, *bsum;
    int2 *edges;
    cudaGetSymbolAddress((void**)&agg,    g_agg);
    cudaGetSymbolAddress((void**)&h,      g_h);
    cudaGetSymbolAddress((void**)&wt,     g_wt);
    cudaGetSymbolAddress((void**)&stats,  g_stats);
    cudaGetSymbolAddress((void**)&deg,    g_deg);
    cudaGetSymbolAddress((void**)&startv, g_startv);
    cudaGetSymbolAddress((void**)&cursor, g_cursor);
    cudaGetSymbolAddress((void**)&bsum,   g_bsum);
    cudaGetSymbolAddress((void**)&edges,  g_edges);

    const int SMEM = (2 * F * F + 2 * BM * ASTR) * (int)sizeof(float);
    cudaFuncSetAttribute(gemm_fused<true>,  cudaFuncAttributeMaxDynamicSharedMemorySize, SMEM);
    cudaFuncSetAttribute(gemm_fused<false>, cudaFuncAttributeMaxDynamicSharedMemorySize, SMEM);

    // ---- CSR build (once, reused by both layers) ----
    cudaMemsetAsync(deg, 0, (N + 1) * sizeof(int));
    cudaMemsetAsync(stats, 0, 2 * F * sizeof(float));

    int eb = (E + 255) / 256;
    hist_kernel<<<eb, 256>>>(ei, E, deg);
    int nchunks = (N + 255) / 256;
    scan1_kernel<<<nchunks, 256>>>(deg, startv, bsum, N);
    scan2_kernel<<<1, 256>>>(bsum, nchunks);
    scan3_kernel<<<nchunks, 256>>>(startv, cursor, bsum, N, E);
    fill_kernel<<<eb, 256>>>(ei, ea, E, cursor, edges);

    transpose_all<<<dim3(4, 4, 4), dim3(32, 8)>>>(W1rel, W1root, W2rel, W2root, wt);

    // ---- layer 1 ----
    int gwb = (N * 32 + 255) / 256;
    gather_kernel<<<gwb, 256>>>(x, startv, edges, agg, N);

    int gblocks = (N + BM - 1) / BM;
    gemm_fused<true><<<gblocks, 256, SMEM>>>(agg, x, wt, wt + F * F, b1, h, N, stats);

    int bnblocks = (N * (F / 4) + 255) / 256;
    bn_rrelu_kernel<<<bnblocks, 256>>>(h, stats, gamma, beta, N);

    // ---- layer 2 ----
    gather_kernel<<<gwb, 256>>>(h, startv, edges, agg, N);

    gemm_fused<false><<<gblocks, 256, SMEM>>>(agg, h, wt + 2 * F * F, wt + 3 * F * F, b2, out, N, nullptr);
}